// round 1
// baseline (speedup 1.0000x reference)
#include <cuda_runtime.h>

#define SEQ   2048
#define BATCH 2
#define NH    16
#define DH    128
#define DM    2048
#define MTOT  (BATCH*SEQ)   // 4096

// Scratch (device globals — allocation-free per harness rules).
__device__ float g_q [BATCH*NH*SEQ*DH];   // [B,H,S,D]
__device__ float g_k [BATCH*NH*SEQ*DH];
__device__ float g_v [BATCH*NH*SEQ*DH];
__device__ float g_ao[BATCH*SEQ*DM];      // attention out, [B,S,H*D]

// ---------------------------------------------------------------------------
// SGEMM 128x128 tile, BK=8, 256 threads, 8x8 per-thread micro-tile.
// MODE 0: C = x @ W_qkv + b_qkv, scattered into g_q/g_k/g_v ([B,H,S,D]).
// MODE 1: C = g_ao @ W_out + b_out -> d_out ([B,S,DM]).
// ---------------------------------------------------------------------------
template<int MODE>
__global__ __launch_bounds__(256)
void sgemm128(const float* __restrict__ A,
              const float* __restrict__ B,
              const float* __restrict__ bias,
              float* __restrict__ C,
              int K, int N)
{
    __shared__ float As[8][128];   // transposed A tile: As[k][m]
    __shared__ float Bs[8][128];

    const int bm  = blockIdx.y, bn = blockIdx.x;
    const int tid = threadIdx.x;
    const int tr  = tid >> 4;          // 0..15 (row group)
    const int tc  = tid & 15;          // 0..15 (col group)
    const int iRA = tid >> 1;          // 0..127
    const int iCA = (tid & 1) << 2;    // 0 or 4
    const int iRB = tid >> 5;          // 0..7
    const int iCB = (tid & 31) << 2;   // 0..124

    const float* Ap   = (MODE == 1) ? (const float*)g_ao : A;
    const float* Arow = Ap + (size_t)(bm*128 + iRA)*K;
    const float* Bp   = B + (size_t)bn*128;

    float acc[8][8];
    #pragma unroll
    for (int i = 0; i < 8; i++)
        #pragma unroll
        for (int j = 0; j < 8; j++) acc[i][j] = 0.f;

    for (int k0 = 0; k0 < K; k0 += 8) {
        float4 a4 = *(const float4*)(Arow + k0 + iCA);
        As[iCA+0][iRA] = a4.x;
        As[iCA+1][iRA] = a4.y;
        As[iCA+2][iRA] = a4.z;
        As[iCA+3][iRA] = a4.w;
        *(float4*)&Bs[iRB][iCB] = *(const float4*)(Bp + (size_t)(k0 + iRB)*N + iCB);
        __syncthreads();

        #pragma unroll
        for (int k = 0; k < 8; k++) {
            float rm[8], rn[8];
            *(float4*)&rm[0] = *(const float4*)&As[k][tr*8];
            *(float4*)&rm[4] = *(const float4*)&As[k][tr*8 + 4];
            *(float4*)&rn[0] = *(const float4*)&Bs[k][tc*8];
            *(float4*)&rn[4] = *(const float4*)&Bs[k][tc*8 + 4];
            #pragma unroll
            for (int i = 0; i < 8; i++)
                #pragma unroll
                for (int j = 0; j < 8; j++)
                    acc[i][j] += rm[i]*rn[j];
        }
        __syncthreads();
    }

    if (MODE == 0) {
        // Each 128-wide column block lies inside exactly one (q/k/v, head) slab.
        const int ncol0 = bn*128;
        const int which = ncol0 >> 11;           // 0=q 1=k 2=v
        const int h     = (ncol0 & 2047) >> 7;   // head
        float* dst = (which == 0) ? g_q : (which == 1) ? g_k : g_v;
        #pragma unroll
        for (int i = 0; i < 8; i++) {
            const int m = bm*128 + tr*8 + i;
            const int b = m >> 11;               // / SEQ
            const int s = m & 2047;              // % SEQ
            float* drow = dst + ((size_t)(b*NH + h)*SEQ + s)*DH;
            #pragma unroll
            for (int j = 0; j < 8; j++) {
                const int d = tc*8 + j;
                drow[d] = acc[i][j] + bias[ncol0 + d];
            }
        }
    } else {
        #pragma unroll
        for (int i = 0; i < 8; i++) {
            const int m = bm*128 + tr*8 + i;
            float* crow = C + (size_t)m*N + bn*128;
            #pragma unroll
            for (int j = 0; j < 8; j++) {
                const int n = tc*8 + j;
                crow[n] = acc[i][j] + bias[bn*128 + n];
            }
        }
    }
}

// ---------------------------------------------------------------------------
// Flash-style causal attention. One CTA per (q-tile of 64, head, batch).
// 256 threads. K/V share one smem tile. Online softmax through smem P.
// ---------------------------------------------------------------------------
#define QPAD 132
#define PPAD 68

__global__ __launch_bounds__(256)
void attn_fwd()
{
    extern __shared__ float smf[];
    float* Qs   = smf;                 // 64*132
    float* KV   = Qs + 64*QPAD;        // 64*132 (K tile, then reused for V)
    float* P    = KV + 64*QPAD;        // 64*68
    float* rowM = P + 64*PPAD;         // 64
    float* rowL = rowM + 64;           // 64
    float* rowC = rowL + 64;           // 64

    const int qt = blockIdx.x, h = blockIdx.y, b = blockIdx.z;
    const int tid = threadIdx.x;
    const int ty  = tid >> 4;          // 0..15
    const int tx  = tid & 15;          // 0..15
    const float scale = 0.088388347648318447f;  // 1/sqrt(128)

    const float* Qg = g_q + ((size_t)(b*NH + h)*SEQ + qt*64)*DH;
    const float* Kg = g_k + ((size_t)(b*NH + h)*SEQ)*DH;
    const float* Vg = g_v + ((size_t)(b*NH + h)*SEQ)*DH;

    // Load scaled Q tile (64x128) via float4, row-coalesced.
    for (int idx = tid; idx < 64*32; idx += 256) {
        const int r = idx >> 5, c4 = idx & 31;
        float4 q = ((const float4*)Qg)[r*32 + c4];
        float* qp = Qs + r*QPAD + c4*4;
        qp[0] = q.x*scale; qp[1] = q.y*scale; qp[2] = q.z*scale; qp[3] = q.w*scale;
    }
    if (tid < 64) { rowM[tid] = -1e30f; rowL[tid] = 0.f; }

    float acc[4][8];
    #pragma unroll
    for (int i = 0; i < 4; i++)
        #pragma unroll
        for (int n = 0; n < 8; n++) acc[i][n] = 0.f;

    for (int kt = 0; kt <= qt; kt++) {
        __syncthreads();  // previous PV done (and Q/stats ready on first iter)

        // Load K tile into KV.
        const float* Kt = Kg + (size_t)(kt*64)*DH;
        for (int idx = tid; idx < 64*32; idx += 256) {
            const int r = idx >> 5, c4 = idx & 31;
            float4 k4 = ((const float4*)Kt)[r*32 + c4];
            float* kp = KV + r*QPAD + c4*4;
            kp[0] = k4.x; kp[1] = k4.y; kp[2] = k4.z; kp[3] = k4.w;
        }
        __syncthreads();

        // S = Q K^T : each thread computes a 4x4 block (rows 16i+ty, cols 16j+tx).
        float s[4][4];
        #pragma unroll
        for (int i = 0; i < 4; i++)
            #pragma unroll
            for (int j = 0; j < 4; j++) s[i][j] = 0.f;

        #pragma unroll 4
        for (int d = 0; d < 128; d++) {
            float qv[4], kv[4];
            #pragma unroll
            for (int i = 0; i < 4; i++) qv[i] = Qs[(16*i + ty)*QPAD + d];
            #pragma unroll
            for (int j = 0; j < 4; j++) kv[j] = KV[(16*j + tx)*QPAD + d];
            #pragma unroll
            for (int i = 0; i < 4; i++)
                #pragma unroll
                for (int j = 0; j < 4; j++)
                    s[i][j] += qv[i]*kv[j];
        }

        if (kt == qt) {  // causal mask on the diagonal tile
            #pragma unroll
            for (int i = 0; i < 4; i++)
                #pragma unroll
                for (int j = 0; j < 4; j++)
                    if (16*j + tx > 16*i + ty) s[i][j] = -1e30f;
        }
        __syncthreads();  // everyone done reading K from KV

        // Store scores to P; concurrently load V tile into KV.
        #pragma unroll
        for (int i = 0; i < 4; i++)
            #pragma unroll
            for (int j = 0; j < 4; j++)
                P[(16*i + ty)*PPAD + (16*j + tx)] = s[i][j];

        const float* Vt = Vg + (size_t)(kt*64)*DH;
        for (int idx = tid; idx < 64*32; idx += 256) {
            const int r = idx >> 5, c4 = idx & 31;
            float4 v4 = ((const float4*)Vt)[r*32 + c4];
            float* vp = KV + r*QPAD + c4*4;
            vp[0] = v4.x; vp[1] = v4.y; vp[2] = v4.z; vp[3] = v4.w;
        }
        __syncthreads();

        // Online softmax: one thread per row.
        if (tid < 64) {
            float* pr = P + tid*PPAD;
            const float mold = rowM[tid];
            float mx = mold;
            #pragma unroll 8
            for (int j = 0; j < 64; j++) mx = fmaxf(mx, pr[j]);
            const float corr = __expf(mold - mx);
            float l = rowL[tid]*corr;
            #pragma unroll 8
            for (int j = 0; j < 64; j++) {
                const float p = __expf(pr[j] - mx);
                pr[j] = p;
                l += p;
            }
            rowM[tid] = mx; rowL[tid] = l; rowC[tid] = corr;
        }
        __syncthreads();

        // Rescale accumulators, then O += P @ V.
        float cf[4];
        #pragma unroll
        for (int i = 0; i < 4; i++) cf[i] = rowC[16*i + ty];
        #pragma unroll
        for (int i = 0; i < 4; i++)
            #pragma unroll
            for (int n = 0; n < 8; n++) acc[i][n] *= cf[i];

        #pragma unroll 2
        for (int kk = 0; kk < 64; kk++) {
            float p[4];
            #pragma unroll
            for (int i = 0; i < 4; i++) p[i] = P[(16*i + ty)*PPAD + kk];
            const float4 va = *(const float4*)&KV[kk*QPAD + tx*8];
            const float4 vb = *(const float4*)&KV[kk*QPAD + tx*8 + 4];
            #pragma unroll
            for (int i = 0; i < 4; i++) {
                acc[i][0] += p[i]*va.x; acc[i][1] += p[i]*va.y;
                acc[i][2] += p[i]*va.z; acc[i][3] += p[i]*va.w;
                acc[i][4] += p[i]*vb.x; acc[i][5] += p[i]*vb.y;
                acc[i][6] += p[i]*vb.z; acc[i][7] += p[i]*vb.w;
            }
        }
    }

    // Normalize and write to [B,S,H*D].
    float* Og = g_ao + ((size_t)(b*SEQ + qt*64))*DM + h*DH;
    #pragma unroll
    for (int i = 0; i < 4; i++) {
        const int r = 16*i + ty;
        const float inv = 1.0f / rowL[r];
        float* orow = Og + (size_t)r*DM + tx*8;
        #pragma unroll
        for (int n = 0; n < 8; n++) orow[n] = acc[i][n]*inv;
    }
}

// ---------------------------------------------------------------------------

extern "C" void kernel_launch(void* const* d_in, const int* in_sizes, int n_in,
                              void* d_out, int out_size)
{
    const float* x    = (const float*)d_in[0];
    const float* Wqkv = (const float*)d_in[1];
    const float* bqkv = (const float*)d_in[2];
    const float* Wout = (const float*)d_in[3];
    const float* bout = (const float*)d_in[4];
    float* out = (float*)d_out;

    const int attn_smem = (64*QPAD*2 + 64*PPAD + 3*64) * (int)sizeof(float);  // 85760 B
    cudaFuncSetAttribute(attn_fwd, cudaFuncAttributeMaxDynamicSharedMemorySize, attn_smem);

    // 1) QKV projection -> g_q/g_k/g_v
    dim3 g1(3*DM/128, MTOT/128);
    sgemm128<0><<<g1, 256>>>(x, Wqkv, bqkv, nullptr, DM, 3*DM);

    // 2) Causal attention -> g_ao
    dim3 g2(SEQ/64, NH, BATCH);
    attn_fwd<<<g2, 256, attn_smem>>>();

    // 3) Output projection -> d_out
    dim3 g3(DM/128, MTOT/128);
    sgemm128<1><<<g3, 256>>>(nullptr, Wout, bout, out, DM, DM);
}

// round 2
// speedup vs baseline: 1.9430x; 1.9430x over previous
#include <cuda_runtime.h>
#include <cstdint>

#define SEQ   2048
#define BATCH 2
#define NH    16
#define DH    128
#define DM    2048
#define MTOT  (BATCH*SEQ)   // 4096

// Scratch (device globals — allocation-free per harness rules).
__device__ float g_q [BATCH*NH*SEQ*DH];   // [B,H,S,D]
__device__ float g_k [BATCH*NH*SEQ*DH];
__device__ float g_v [BATCH*NH*SEQ*DH];
__device__ float g_ao[BATCH*SEQ*DM];      // attention out, [B,S,H*D]

__device__ __forceinline__ float to_tf32(float x) {
    // Round-to-nearest tf32: avoids the systematic truncation bias of raw HMMA reads.
    asm("cvt.rna.tf32.f32 %0, %0;" : "+f"(x));
    return x;
}

__device__ __forceinline__ void mma_tf32(float* c, const uint32_t* a, const uint32_t* b) {
    asm volatile(
        "mma.sync.aligned.m16n8k8.row.col.f32.tf32.tf32.f32 "
        "{%0,%1,%2,%3}, {%4,%5,%6,%7}, {%8,%9}, {%0,%1,%2,%3};"
        : "+f"(c[0]), "+f"(c[1]), "+f"(c[2]), "+f"(c[3])
        : "r"(a[0]), "r"(a[1]), "r"(a[2]), "r"(a[3]), "r"(b[0]), "r"(b[1]));
}

// ---------------------------------------------------------------------------
// TF32 tensor-core GEMM. 128x128 CTA tile, BK=16, 256 threads (8 warps, 2x4).
// Warp tile 64x32 = 4x4 grid of m16n8k8 mma.
// MODE 0: C = x @ W_qkv + b_qkv -> scatter into g_q/g_k/g_v ([B,H,S,D]).
// MODE 1: C = g_ao @ W_out + b_out -> d_out ([B,S,DM]).
// ---------------------------------------------------------------------------
template<int MODE>
__global__ __launch_bounds__(256, 2)
void tgemm(const float* __restrict__ A,
           const float* __restrict__ Bg,
           const float* __restrict__ bias,
           float* __restrict__ C,
           int K, int N)
{
    __shared__ float As[16][136];   // As[k][m], pitch 136 -> conflict-free frag LDS
    __shared__ float Bs[16][136];   // Bs[k][n]

    const int tid  = threadIdx.x;
    const int bm   = blockIdx.y, bn = blockIdx.x;
    const int lane = tid & 31;
    const int wid  = tid >> 5;
    const int wm   = wid & 1;          // warp row (0..1) -> 64 rows each
    const int wn   = wid >> 1;         // warp col (0..3) -> 32 cols each
    const int gid  = lane >> 2;        // 0..7
    const int tig  = lane & 3;         // 0..3

    // Global load mapping
    const int arow = tid >> 1;          // 0..127
    const int acol = (tid & 1) * 8;     // 0 or 8
    const int brow = tid >> 4;          // 0..15
    const int bcol = (tid & 15) * 4;    // 0..60

    const float* Ap    = (MODE == 1) ? (const float*)g_ao : A;
    const float* Aload = Ap + (size_t)(bm*128 + arow)*K + acol;
    const float* Bload = Bg + (size_t)brow*N + bn*128 + bcol;

    float acc[4][4][4];
    #pragma unroll
    for (int mi = 0; mi < 4; mi++)
        #pragma unroll
        for (int nj = 0; nj < 4; nj++)
            #pragma unroll
            for (int f = 0; f < 4; f++) acc[mi][nj][f] = 0.f;

    // ---- prologue: tile 0 ----
    {
        float4 a0 = *(const float4*)(Aload);
        float4 a1 = *(const float4*)(Aload + 4);
        float4 b0 = *(const float4*)(Bload);
        float4 b1 = *(const float4*)(Bload + 64);
        As[acol+0][arow] = to_tf32(a0.x); As[acol+1][arow] = to_tf32(a0.y);
        As[acol+2][arow] = to_tf32(a0.z); As[acol+3][arow] = to_tf32(a0.w);
        As[acol+4][arow] = to_tf32(a1.x); As[acol+5][arow] = to_tf32(a1.y);
        As[acol+6][arow] = to_tf32(a1.z); As[acol+7][arow] = to_tf32(a1.w);
        Bs[brow][bcol+0]  = to_tf32(b0.x); Bs[brow][bcol+1]  = to_tf32(b0.y);
        Bs[brow][bcol+2]  = to_tf32(b0.z); Bs[brow][bcol+3]  = to_tf32(b0.w);
        Bs[brow][bcol+64] = to_tf32(b1.x); Bs[brow][bcol+65] = to_tf32(b1.y);
        Bs[brow][bcol+66] = to_tf32(b1.z); Bs[brow][bcol+67] = to_tf32(b1.w);
    }
    __syncthreads();

    for (int k0 = 16; k0 <= K; k0 += 16) {
        const bool nxt = k0 < K;
        float4 na0, na1, nb0, nb1;
        if (nxt) {
            na0 = *(const float4*)(Aload + k0);
            na1 = *(const float4*)(Aload + k0 + 4);
            nb0 = *(const float4*)(Bload + (size_t)k0*N);
            nb1 = *(const float4*)(Bload + (size_t)k0*N + 64);
        }

        // ---- compute current tile: 2 k-steps of 8 ----
        #pragma unroll
        for (int ks = 0; ks < 2; ks++) {
            const int kk = ks*8;
            uint32_t af[4][4];
            uint32_t bf[4][2];
            #pragma unroll
            for (int mi = 0; mi < 4; mi++) {
                const int r = wm*64 + mi*16 + gid;
                af[mi][0] = __float_as_uint(As[kk+tig  ][r]);
                af[mi][1] = __float_as_uint(As[kk+tig  ][r+8]);
                af[mi][2] = __float_as_uint(As[kk+tig+4][r]);
                af[mi][3] = __float_as_uint(As[kk+tig+4][r+8]);
            }
            #pragma unroll
            for (int nj = 0; nj < 4; nj++) {
                const int c = wn*32 + nj*8 + gid;
                bf[nj][0] = __float_as_uint(Bs[kk+tig  ][c]);
                bf[nj][1] = __float_as_uint(Bs[kk+tig+4][c]);
            }
            #pragma unroll
            for (int mi = 0; mi < 4; mi++)
                #pragma unroll
                for (int nj = 0; nj < 4; nj++)
                    mma_tf32(acc[mi][nj], af[mi], bf[nj]);
        }

        if (nxt) {
            __syncthreads();
            As[acol+0][arow] = to_tf32(na0.x); As[acol+1][arow] = to_tf32(na0.y);
            As[acol+2][arow] = to_tf32(na0.z); As[acol+3][arow] = to_tf32(na0.w);
            As[acol+4][arow] = to_tf32(na1.x); As[acol+5][arow] = to_tf32(na1.y);
            As[acol+6][arow] = to_tf32(na1.z); As[acol+7][arow] = to_tf32(na1.w);
            Bs[brow][bcol+0]  = to_tf32(nb0.x); Bs[brow][bcol+1]  = to_tf32(nb0.y);
            Bs[brow][bcol+2]  = to_tf32(nb0.z); Bs[brow][bcol+3]  = to_tf32(nb0.w);
            Bs[brow][bcol+64] = to_tf32(nb1.x); Bs[brow][bcol+65] = to_tf32(nb1.y);
            Bs[brow][bcol+66] = to_tf32(nb1.z); Bs[brow][bcol+67] = to_tf32(nb1.w);
            __syncthreads();
        }
    }

    // ---- epilogue ----
    // bias for this thread's 8 columns: cols = bn*128 + wn*32 + nj*8 + tig*2 + {0,1}
    float2 bb[4];
    #pragma unroll
    for (int nj = 0; nj < 4; nj++)
        bb[nj] = *(const float2*)&bias[bn*128 + wn*32 + nj*8 + tig*2];

    if (MODE == 0) {
        const int ncol0 = bn*128;
        const int which = ncol0 >> 11;           // 0=q 1=k 2=v
        const int h     = (ncol0 & 2047) >> 7;   // head
        float* dst = (which == 0) ? g_q : (which == 1) ? g_k : g_v;
        #pragma unroll
        for (int mi = 0; mi < 4; mi++) {
            #pragma unroll
            for (int half = 0; half < 2; half++) {
                const int m = bm*128 + wm*64 + mi*16 + gid + half*8;
                const int b = m >> 11;           // / SEQ
                const int s = m & 2047;          // % SEQ
                float* drow = dst + ((size_t)(b*NH + h)*SEQ + s)*DH;
                #pragma unroll
                for (int nj = 0; nj < 4; nj++) {
                    const int d = wn*32 + nj*8 + tig*2;
                    float2 v;
                    v.x = acc[mi][nj][half*2+0] + bb[nj].x;
                    v.y = acc[mi][nj][half*2+1] + bb[nj].y;
                    *(float2*)&drow[d] = v;
                }
            }
        }
    } else {
        #pragma unroll
        for (int mi = 0; mi < 4; mi++) {
            #pragma unroll
            for (int half = 0; half < 2; half++) {
                const int m = bm*128 + wm*64 + mi*16 + gid + half*8;
                float* crow = C + (size_t)m*N + bn*128;
                #pragma unroll
                for (int nj = 0; nj < 4; nj++) {
                    const int n = wn*32 + nj*8 + tig*2;
                    float2 v;
                    v.x = acc[mi][nj][half*2+0] + bb[nj].x;
                    v.y = acc[mi][nj][half*2+1] + bb[nj].y;
                    *(float2*)&crow[n] = v;
                }
            }
        }
    }
}

// ---------------------------------------------------------------------------
// Flash-style causal attention (exact fp32, unchanged from R1).
// One CTA per (q-tile of 64, head, batch). 256 threads.
// ---------------------------------------------------------------------------
#define QPAD 132
#define PPAD 68

__global__ __launch_bounds__(256)
void attn_fwd()
{
    extern __shared__ float smf[];
    float* Qs   = smf;                 // 64*132
    float* KV   = Qs + 64*QPAD;        // 64*132 (K tile, then reused for V)
    float* P    = KV + 64*QPAD;        // 64*68
    float* rowM = P + 64*PPAD;         // 64
    float* rowL = rowM + 64;           // 64
    float* rowC = rowL + 64;           // 64

    const int qt = blockIdx.x, h = blockIdx.y, b = blockIdx.z;
    const int tid = threadIdx.x;
    const int ty  = tid >> 4;          // 0..15
    const int tx  = tid & 15;          // 0..15
    const float scale = 0.088388347648318447f;  // 1/sqrt(128)

    const float* Qg = g_q + ((size_t)(b*NH + h)*SEQ + qt*64)*DH;
    const float* Kg = g_k + ((size_t)(b*NH + h)*SEQ)*DH;
    const float* Vg = g_v + ((size_t)(b*NH + h)*SEQ)*DH;

    for (int idx = tid; idx < 64*32; idx += 256) {
        const int r = idx >> 5, c4 = idx & 31;
        float4 q = ((const float4*)Qg)[r*32 + c4];
        float* qp = Qs + r*QPAD + c4*4;
        qp[0] = q.x*scale; qp[1] = q.y*scale; qp[2] = q.z*scale; qp[3] = q.w*scale;
    }
    if (tid < 64) { rowM[tid] = -1e30f; rowL[tid] = 0.f; }

    float acc[4][8];
    #pragma unroll
    for (int i = 0; i < 4; i++)
        #pragma unroll
        for (int n = 0; n < 8; n++) acc[i][n] = 0.f;

    for (int kt = 0; kt <= qt; kt++) {
        __syncthreads();

        const float* Kt = Kg + (size_t)(kt*64)*DH;
        for (int idx = tid; idx < 64*32; idx += 256) {
            const int r = idx >> 5, c4 = idx & 31;
            float4 k4 = ((const float4*)Kt)[r*32 + c4];
            float* kp = KV + r*QPAD + c4*4;
            kp[0] = k4.x; kp[1] = k4.y; kp[2] = k4.z; kp[3] = k4.w;
        }
        __syncthreads();

        float s[4][4];
        #pragma unroll
        for (int i = 0; i < 4; i++)
            #pragma unroll
            for (int j = 0; j < 4; j++) s[i][j] = 0.f;

        #pragma unroll 4
        for (int d = 0; d < 128; d++) {
            float qv[4], kv[4];
            #pragma unroll
            for (int i = 0; i < 4; i++) qv[i] = Qs[(16*i + ty)*QPAD + d];
            #pragma unroll
            for (int j = 0; j < 4; j++) kv[j] = KV[(16*j + tx)*QPAD + d];
            #pragma unroll
            for (int i = 0; i < 4; i++)
                #pragma unroll
                for (int j = 0; j < 4; j++)
                    s[i][j] += qv[i]*kv[j];
        }

        if (kt == qt) {
            #pragma unroll
            for (int i = 0; i < 4; i++)
                #pragma unroll
                for (int j = 0; j < 4; j++)
                    if (16*j + tx > 16*i + ty) s[i][j] = -1e30f;
        }
        __syncthreads();

        #pragma unroll
        for (int i = 0; i < 4; i++)
            #pragma unroll
            for (int j = 0; j < 4; j++)
                P[(16*i + ty)*PPAD + (16*j + tx)] = s[i][j];

        const float* Vt = Vg + (size_t)(kt*64)*DH;
        for (int idx = tid; idx < 64*32; idx += 256) {
            const int r = idx >> 5, c4 = idx & 31;
            float4 v4 = ((const float4*)Vt)[r*32 + c4];
            float* vp = KV + r*QPAD + c4*4;
            vp[0] = v4.x; vp[1] = v4.y; vp[2] = v4.z; vp[3] = v4.w;
        }
        __syncthreads();

        if (tid < 64) {
            float* pr = P + tid*PPAD;
            const float mold = rowM[tid];
            float mx = mold;
            #pragma unroll 8
            for (int j = 0; j < 64; j++) mx = fmaxf(mx, pr[j]);
            const float corr = __expf(mold - mx);
            float l = rowL[tid]*corr;
            #pragma unroll 8
            for (int j = 0; j < 64; j++) {
                const float p = __expf(pr[j] - mx);
                pr[j] = p;
                l += p;
            }
            rowM[tid] = mx; rowL[tid] = l; rowC[tid] = corr;
        }
        __syncthreads();

        float cf[4];
        #pragma unroll
        for (int i = 0; i < 4; i++) cf[i] = rowC[16*i + ty];
        #pragma unroll
        for (int i = 0; i < 4; i++)
            #pragma unroll
            for (int n = 0; n < 8; n++) acc[i][n] *= cf[i];

        #pragma unroll 2
        for (int kk = 0; kk < 64; kk++) {
            float p[4];
            #pragma unroll
            for (int i = 0; i < 4; i++) p[i] = P[(16*i + ty)*PPAD + kk];
            const float4 va = *(const float4*)&KV[kk*QPAD + tx*8];
            const float4 vb = *(const float4*)&KV[kk*QPAD + tx*8 + 4];
            #pragma unroll
            for (int i = 0; i < 4; i++) {
                acc[i][0] += p[i]*va.x; acc[i][1] += p[i]*va.y;
                acc[i][2] += p[i]*va.z; acc[i][3] += p[i]*va.w;
                acc[i][4] += p[i]*vb.x; acc[i][5] += p[i]*vb.y;
                acc[i][6] += p[i]*vb.z; acc[i][7] += p[i]*vb.w;
            }
        }
    }

    float* Og = g_ao + ((size_t)(b*SEQ + qt*64))*DM + h*DH;
    #pragma unroll
    for (int i = 0; i < 4; i++) {
        const int r = 16*i + ty;
        const float inv = 1.0f / rowL[r];
        float* orow = Og + (size_t)r*DM + tx*8;
        #pragma unroll
        for (int n = 0; n < 8; n++) orow[n] = acc[i][n]*inv;
    }
}

// ---------------------------------------------------------------------------

extern "C" void kernel_launch(void* const* d_in, const int* in_sizes, int n_in,
                              void* d_out, int out_size)
{
    const float* x    = (const float*)d_in[0];
    const float* Wqkv = (const float*)d_in[1];
    const float* bqkv = (const float*)d_in[2];
    const float* Wout = (const float*)d_in[3];
    const float* bout = (const float*)d_in[4];
    float* out = (float*)d_out;

    const int attn_smem = (64*QPAD*2 + 64*PPAD + 3*64) * (int)sizeof(float);  // 85760 B
    cudaFuncSetAttribute(attn_fwd, cudaFuncAttributeMaxDynamicSharedMemorySize, attn_smem);

    // 1) QKV projection -> g_q/g_k/g_v  (TF32 tensor cores)
    dim3 g1(3*DM/128, MTOT/128);
    tgemm<0><<<g1, 256>>>(x, Wqkv, bqkv, nullptr, DM, 3*DM);

    // 2) Causal attention -> g_ao  (exact fp32)
    dim3 g2(SEQ/64, NH, BATCH);
    attn_fwd<<<g2, 256, attn_smem>>>();

    // 3) Output projection -> d_out  (TF32 tensor cores)
    dim3 g3(DM/128, MTOT/128);
    tgemm<1><<<g3, 256>>>(nullptr, Wout, bout, out, DM, DM);
}

// round 3
// speedup vs baseline: 3.1013x; 1.5961x over previous
#include <cuda_runtime.h>
#include <cstdint>

#define SEQ   2048
#define BATCH 2
#define NH    16
#define DH    128
#define DM    2048
#define MTOT  (BATCH*SEQ)   // 4096

// Scratch (device globals — allocation-free per harness rules).
__device__ float g_q [BATCH*NH*SEQ*DH];   // [B,H,S,D]
__device__ float g_k [BATCH*NH*SEQ*DH];
__device__ float g_v [BATCH*NH*SEQ*DH];
__device__ float g_ao[BATCH*SEQ*DM];      // attention out, [B,S,H*D]

__device__ __forceinline__ float to_tf32(float x) {
    asm("cvt.rna.tf32.f32 %0, %0;" : "+f"(x));
    return x;
}

__device__ __forceinline__ void mma_tf32(float* c, const uint32_t* a, const uint32_t* b) {
    asm volatile(
        "mma.sync.aligned.m16n8k8.row.col.f32.tf32.tf32.f32 "
        "{%0,%1,%2,%3}, {%4,%5,%6,%7}, {%8,%9}, {%0,%1,%2,%3};"
        : "+f"(c[0]), "+f"(c[1]), "+f"(c[2]), "+f"(c[3])
        : "r"(a[0]), "r"(a[1]), "r"(a[2]), "r"(a[3]), "r"(b[0]), "r"(b[1]));
}

__device__ __forceinline__ void cp16(uint32_t dst, const void* src) {
    asm volatile("cp.async.cg.shared.global [%0], [%1], 16;" :: "r"(dst), "l"(src));
}
__device__ __forceinline__ void cp_commit() { asm volatile("cp.async.commit_group;"); }
__device__ __forceinline__ void cp_wait1()  { asm volatile("cp.async.wait_group 1;"); }

// ---------------------------------------------------------------------------
// TF32 tensor-core GEMM (unchanged from R2). 128x128 CTA tile, BK=16.
// ---------------------------------------------------------------------------
template<int MODE>
__global__ __launch_bounds__(256, 2)
void tgemm(const float* __restrict__ A,
           const float* __restrict__ Bg,
           const float* __restrict__ bias,
           float* __restrict__ C,
           int K, int N)
{
    __shared__ float As[16][136];
    __shared__ float Bs[16][136];

    const int tid  = threadIdx.x;
    const int bm   = blockIdx.y, bn = blockIdx.x;
    const int lane = tid & 31;
    const int wid  = tid >> 5;
    const int wm   = wid & 1;
    const int wn   = wid >> 1;
    const int gid  = lane >> 2;
    const int tig  = lane & 3;

    const int arow = tid >> 1;
    const int acol = (tid & 1) * 8;
    const int brow = tid >> 4;
    const int bcol = (tid & 15) * 4;

    const float* Ap    = (MODE == 1) ? (const float*)g_ao : A;
    const float* Aload = Ap + (size_t)(bm*128 + arow)*K + acol;
    const float* Bload = Bg + (size_t)brow*N + bn*128 + bcol;

    float acc[4][4][4];
    #pragma unroll
    for (int mi = 0; mi < 4; mi++)
        #pragma unroll
        for (int nj = 0; nj < 4; nj++)
            #pragma unroll
            for (int f = 0; f < 4; f++) acc[mi][nj][f] = 0.f;

    {
        float4 a0 = *(const float4*)(Aload);
        float4 a1 = *(const float4*)(Aload + 4);
        float4 b0 = *(const float4*)(Bload);
        float4 b1 = *(const float4*)(Bload + 64);
        As[acol+0][arow] = to_tf32(a0.x); As[acol+1][arow] = to_tf32(a0.y);
        As[acol+2][arow] = to_tf32(a0.z); As[acol+3][arow] = to_tf32(a0.w);
        As[acol+4][arow] = to_tf32(a1.x); As[acol+5][arow] = to_tf32(a1.y);
        As[acol+6][arow] = to_tf32(a1.z); As[acol+7][arow] = to_tf32(a1.w);
        Bs[brow][bcol+0]  = to_tf32(b0.x); Bs[brow][bcol+1]  = to_tf32(b0.y);
        Bs[brow][bcol+2]  = to_tf32(b0.z); Bs[brow][bcol+3]  = to_tf32(b0.w);
        Bs[brow][bcol+64] = to_tf32(b1.x); Bs[brow][bcol+65] = to_tf32(b1.y);
        Bs[brow][bcol+66] = to_tf32(b1.z); Bs[brow][bcol+67] = to_tf32(b1.w);
    }
    __syncthreads();

    for (int k0 = 16; k0 <= K; k0 += 16) {
        const bool nxt = k0 < K;
        float4 na0, na1, nb0, nb1;
        if (nxt) {
            na0 = *(const float4*)(Aload + k0);
            na1 = *(const float4*)(Aload + k0 + 4);
            nb0 = *(const float4*)(Bload + (size_t)k0*N);
            nb1 = *(const float4*)(Bload + (size_t)k0*N + 64);
        }

        #pragma unroll
        for (int ks = 0; ks < 2; ks++) {
            const int kk = ks*8;
            uint32_t af[4][4];
            uint32_t bf[4][2];
            #pragma unroll
            for (int mi = 0; mi < 4; mi++) {
                const int r = wm*64 + mi*16 + gid;
                af[mi][0] = __float_as_uint(As[kk+tig  ][r]);
                af[mi][1] = __float_as_uint(As[kk+tig  ][r+8]);
                af[mi][2] = __float_as_uint(As[kk+tig+4][r]);
                af[mi][3] = __float_as_uint(As[kk+tig+4][r+8]);
            }
            #pragma unroll
            for (int nj = 0; nj < 4; nj++) {
                const int c = wn*32 + nj*8 + gid;
                bf[nj][0] = __float_as_uint(Bs[kk+tig  ][c]);
                bf[nj][1] = __float_as_uint(Bs[kk+tig+4][c]);
            }
            #pragma unroll
            for (int mi = 0; mi < 4; mi++)
                #pragma unroll
                for (int nj = 0; nj < 4; nj++)
                    mma_tf32(acc[mi][nj], af[mi], bf[nj]);
        }

        if (nxt) {
            __syncthreads();
            As[acol+0][arow] = to_tf32(na0.x); As[acol+1][arow] = to_tf32(na0.y);
            As[acol+2][arow] = to_tf32(na0.z); As[acol+3][arow] = to_tf32(na0.w);
            As[acol+4][arow] = to_tf32(na1.x); As[acol+5][arow] = to_tf32(na1.y);
            As[acol+6][arow] = to_tf32(na1.z); As[acol+7][arow] = to_tf32(na1.w);
            Bs[brow][bcol+0]  = to_tf32(nb0.x); Bs[brow][bcol+1]  = to_tf32(nb0.y);
            Bs[brow][bcol+2]  = to_tf32(nb0.z); Bs[brow][bcol+3]  = to_tf32(nb0.w);
            Bs[brow][bcol+64] = to_tf32(nb1.x); Bs[brow][bcol+65] = to_tf32(nb1.y);
            Bs[brow][bcol+66] = to_tf32(nb1.z); Bs[brow][bcol+67] = to_tf32(nb1.w);
            __syncthreads();
        }
    }

    float2 bb[4];
    #pragma unroll
    for (int nj = 0; nj < 4; nj++)
        bb[nj] = *(const float2*)&bias[bn*128 + wn*32 + nj*8 + tig*2];

    if (MODE == 0) {
        const int ncol0 = bn*128;
        const int which = ncol0 >> 11;
        const int h     = (ncol0 & 2047) >> 7;
        float* dst = (which == 0) ? g_q : (which == 1) ? g_k : g_v;
        #pragma unroll
        for (int mi = 0; mi < 4; mi++) {
            #pragma unroll
            for (int half = 0; half < 2; half++) {
                const int m = bm*128 + wm*64 + mi*16 + gid + half*8;
                const int b = m >> 11;
                const int s = m & 2047;
                float* drow = dst + ((size_t)(b*NH + h)*SEQ + s)*DH;
                #pragma unroll
                for (int nj = 0; nj < 4; nj++) {
                    const int d = wn*32 + nj*8 + tig*2;
                    float2 v;
                    v.x = acc[mi][nj][half*2+0] + bb[nj].x;
                    v.y = acc[mi][nj][half*2+1] + bb[nj].y;
                    *(float2*)&drow[d] = v;
                }
            }
        }
    } else {
        #pragma unroll
        for (int mi = 0; mi < 4; mi++) {
            #pragma unroll
            for (int half = 0; half < 2; half++) {
                const int m = bm*128 + wm*64 + mi*16 + gid + half*8;
                float* crow = C + (size_t)m*N + bn*128;
                #pragma unroll
                for (int nj = 0; nj < 4; nj++) {
                    const int n = wn*32 + nj*8 + tig*2;
                    float2 v;
                    v.x = acc[mi][nj][half*2+0] + bb[nj].x;
                    v.y = acc[mi][nj][half*2+1] + bb[nj].y;
                    *(float2*)&crow[n] = v;
                }
            }
        }
    }
}

// ---------------------------------------------------------------------------
// Tensor-core flash attention (TF32). One CTA per (128 q-rows, h, b).
// 8 warps; warp w owns q-rows [w*16, w*16+16). K-tiles of 64, cp.async
// double-buffered. Softmax fully in registers (quad shfl reductions).
// ---------------------------------------------------------------------------
#define QP 132   // Q smem pitch (conflict-free A-frag loads: 4*gid+tig)
#define KP 132   // K smem pitch (conflict-free B-frag loads: 4*gid+tig)
#define VP 136   // V smem pitch (conflict-free B-frag loads: 8*tig+gid)

#define ATTN_SMEM ((128*QP + 2*64*KP + 2*64*VP) * 4)   // 204800 B

__global__ __launch_bounds__(256, 1)
void attn_tc()
{
    extern __shared__ float sm[];
    float* Qs = sm;                   // 128 x QP
    float* Ks = Qs + 128*QP;          // 2 x 64 x KP
    float* Vs = Ks + 2*64*KP;         // 2 x 64 x VP

    const int qt  = (int)(gridDim.x - 1 - blockIdx.x);   // heavy tiles first
    const int h   = blockIdx.y, b = blockIdx.z;
    const int tid = threadIdx.x;
    const int lane = tid & 31;
    const int wid  = tid >> 5;
    const int gid  = lane >> 2;   // 0..7
    const int tig  = lane & 3;    // 0..3
    const float scale = 0.088388347648318447f;  // 1/sqrt(128)

    const float* Qg = g_q + ((size_t)(b*NH + h)*SEQ + qt*128)*DH;
    const float* Kg = g_k + ((size_t)(b*NH + h)*SEQ)*DH;
    const float* Vg = g_v + ((size_t)(b*NH + h)*SEQ)*DH;

    const uint32_t smb   = (uint32_t)__cvta_generic_to_shared(sm);
    const uint32_t ks_b  = smb + 128*QP*4;
    const uint32_t vs_b  = ks_b + 2*64*KP*4;

    const int nkt = 2*qt + 2;   // k-tiles of 64 covering cols [0, qt*128+128)

    // ---- issue cp.async for tile 0 ----
    {
        #pragma unroll
        for (int t = 0; t < 8; t++) {
            const int e = tid + t*256;          // 16B chunk id, 0..2047
            const int r = e >> 5, c = (e & 31) << 2;
            cp16(ks_b + (uint32_t)(r*KP + c)*4, Kg + r*128 + c);
            cp16(vs_b + (uint32_t)(r*VP + c)*4, Vg + r*128 + c);
        }
        cp_commit();
    }

    // ---- load Q tile (scale + tf32) ----
    for (int idx = tid; idx < 128*32; idx += 256) {
        const int r = idx >> 5, c = (idx & 31) << 2;
        float4 q = *(const float4*)(Qg + r*128 + c);
        float* qp = Qs + r*QP + c;
        qp[0] = to_tf32(q.x*scale); qp[1] = to_tf32(q.y*scale);
        qp[2] = to_tf32(q.z*scale); qp[3] = to_tf32(q.w*scale);
    }
    __syncthreads();

    // ---- Q fragments in registers: 16 k-blocks x 4 regs ----
    uint32_t qa[16][4];
    {
        const int r0 = wid*16 + gid;
        #pragma unroll
        for (int kb = 0; kb < 16; kb++) {
            qa[kb][0] = __float_as_uint(Qs[(r0    )*QP + kb*8 + tig    ]);
            qa[kb][1] = __float_as_uint(Qs[(r0 + 8)*QP + kb*8 + tig    ]);
            qa[kb][2] = __float_as_uint(Qs[(r0    )*QP + kb*8 + tig + 4]);
            qa[kb][3] = __float_as_uint(Qs[(r0 + 8)*QP + kb*8 + tig + 4]);
        }
    }

    float oacc[16][4];
    #pragma unroll
    for (int nv = 0; nv < 16; nv++)
        #pragma unroll
        for (int f = 0; f < 4; f++) oacc[nv][f] = 0.f;
    float m0 = -1e30f, m1 = -1e30f, l0 = 0.f, l1 = 0.f;

    const int r0g = qt*128 + wid*16 + gid;   // global q row (thread's row 0)
    const int r1g = r0g + 8;

    for (int kt = 0; kt < nkt; kt++) {
        // ---- prefetch tile kt+1 (empty group when none: keeps wait depth fixed) ----
        if (kt + 1 < nkt) {
            const int nb = (kt + 1) & 1;
            const float* Kt = Kg + (size_t)(kt+1)*64*DH;
            const float* Vt = Vg + (size_t)(kt+1)*64*DH;
            const uint32_t kd = ks_b + (uint32_t)(nb*64*KP)*4;
            const uint32_t vd = vs_b + (uint32_t)(nb*64*VP)*4;
            #pragma unroll
            for (int t = 0; t < 8; t++) {
                const int e = tid + t*256;
                const int r = e >> 5, c = (e & 31) << 2;
                cp16(kd + (uint32_t)(r*KP + c)*4, Kt + r*128 + c);
                cp16(vd + (uint32_t)(r*VP + c)*4, Vt + r*128 + c);
            }
        }
        cp_commit();
        cp_wait1();          // tile kt arrived
        __syncthreads();

        // ---- in-place RN tf32 conversion of K/V tile kt ----
        const int buf = kt & 1;
        float* Kb = Ks + buf*64*KP;
        float* Vb = Vs + buf*64*VP;
        for (int idx = tid; idx < 64*128; idx += 256) {
            const int r = idx >> 7, c = idx & 127;
            Kb[r*KP + c] = to_tf32(Kb[r*KP + c]);
            Vb[r*VP + c] = to_tf32(Vb[r*VP + c]);
        }
        __syncthreads();

        // ---- S = Q K^T  (16x64 per warp) ----
        float sacc[8][4];
        #pragma unroll
        for (int nb = 0; nb < 8; nb++)
            #pragma unroll
            for (int f = 0; f < 4; f++) sacc[nb][f] = 0.f;

        #pragma unroll
        for (int ks = 0; ks < 16; ks++) {
            uint32_t bf[8][2];
            #pragma unroll
            for (int nb = 0; nb < 8; nb++) {
                bf[nb][0] = __float_as_uint(Kb[(nb*8 + gid)*KP + ks*8 + tig    ]);
                bf[nb][1] = __float_as_uint(Kb[(nb*8 + gid)*KP + ks*8 + tig + 4]);
            }
            #pragma unroll
            for (int nb = 0; nb < 8; nb++)
                mma_tf32(sacc[nb], qa[ks], bf[nb]);
        }

        // ---- causal mask (only when tile crosses the diagonal for this warp) ----
        if (kt*64 + 63 > qt*128 + wid*16) {
            #pragma unroll
            for (int nb = 0; nb < 8; nb++) {
                const int c0 = kt*64 + nb*8 + 2*tig;
                const int c1 = c0 + 1;
                if (c0 > r0g) sacc[nb][0] = -1e30f;
                if (c1 > r0g) sacc[nb][1] = -1e30f;
                if (c0 > r1g) sacc[nb][2] = -1e30f;
                if (c1 > r1g) sacc[nb][3] = -1e30f;
            }
        }

        // ---- online softmax (rows warp-local; quad reductions) ----
        float mx0 = -1e30f, mx1 = -1e30f;
        #pragma unroll
        for (int nb = 0; nb < 8; nb++) {
            mx0 = fmaxf(mx0, fmaxf(sacc[nb][0], sacc[nb][1]));
            mx1 = fmaxf(mx1, fmaxf(sacc[nb][2], sacc[nb][3]));
        }
        mx0 = fmaxf(mx0, __shfl_xor_sync(0xffffffffu, mx0, 1));
        mx0 = fmaxf(mx0, __shfl_xor_sync(0xffffffffu, mx0, 2));
        mx1 = fmaxf(mx1, __shfl_xor_sync(0xffffffffu, mx1, 1));
        mx1 = fmaxf(mx1, __shfl_xor_sync(0xffffffffu, mx1, 2));

        const float mn0 = fmaxf(m0, mx0), mn1 = fmaxf(m1, mx1);
        const float cr0 = __expf(m0 - mn0), cr1 = __expf(m1 - mn1);
        m0 = mn0; m1 = mn1;

        float rs0 = 0.f, rs1 = 0.f;
        #pragma unroll
        for (int nb = 0; nb < 8; nb++) {
            sacc[nb][0] = __expf(sacc[nb][0] - mn0); rs0 += sacc[nb][0];
            sacc[nb][1] = __expf(sacc[nb][1] - mn0); rs0 += sacc[nb][1];
            sacc[nb][2] = __expf(sacc[nb][2] - mn1); rs1 += sacc[nb][2];
            sacc[nb][3] = __expf(sacc[nb][3] - mn1); rs1 += sacc[nb][3];
        }
        rs0 += __shfl_xor_sync(0xffffffffu, rs0, 1);
        rs0 += __shfl_xor_sync(0xffffffffu, rs0, 2);
        rs1 += __shfl_xor_sync(0xffffffffu, rs1, 1);
        rs1 += __shfl_xor_sync(0xffffffffu, rs1, 2);
        l0 = l0*cr0 + rs0;
        l1 = l1*cr1 + rs1;

        #pragma unroll
        for (int nv = 0; nv < 16; nv++) {
            oacc[nv][0] *= cr0; oacc[nv][1] *= cr0;
            oacc[nv][2] *= cr1; oacc[nv][3] *= cr1;
        }

        // ---- O += P V : convert P (C-layout) -> A-frags via quad shuffles ----
        const int srcLo = (lane & ~3) | (tig >> 1);
        const int srcHi = srcLo + 2;
        #pragma unroll
        for (int kb = 0; kb < 8; kb++) {
            const float t0 = __shfl_sync(0xffffffffu, sacc[kb][0], srcLo);
            const float t1 = __shfl_sync(0xffffffffu, sacc[kb][1], srcLo);
            const float t2 = __shfl_sync(0xffffffffu, sacc[kb][2], srcLo);
            const float t3 = __shfl_sync(0xffffffffu, sacc[kb][3], srcLo);
            const float u0 = __shfl_sync(0xffffffffu, sacc[kb][0], srcHi);
            const float u1 = __shfl_sync(0xffffffffu, sacc[kb][1], srcHi);
            const float u2 = __shfl_sync(0xffffffffu, sacc[kb][2], srcHi);
            const float u3 = __shfl_sync(0xffffffffu, sacc[kb][3], srcHi);
            uint32_t pa[4];
            pa[0] = __float_as_uint(to_tf32((tig & 1) ? t1 : t0));
            pa[1] = __float_as_uint(to_tf32((tig & 1) ? t3 : t2));
            pa[2] = __float_as_uint(to_tf32((tig & 1) ? u1 : u0));
            pa[3] = __float_as_uint(to_tf32((tig & 1) ? u3 : u2));
            #pragma unroll
            for (int nv = 0; nv < 16; nv++) {
                uint32_t vb[2];
                vb[0] = __float_as_uint(Vb[(kb*8 + tig    )*VP + nv*8 + gid]);
                vb[1] = __float_as_uint(Vb[(kb*8 + tig + 4)*VP + nv*8 + gid]);
                mma_tf32(oacc[nv], pa, vb);
            }
        }
        __syncthreads();   // all warps done with buf before it is refilled (kt+2)
    }

    // ---- normalize + write [B,S,DM] ----
    const float inv0 = 1.0f / l0, inv1 = 1.0f / l1;
    float* O0 = g_ao + ((size_t)(b*SEQ + r0g))*DM + h*DH;
    float* O1 = O0 + (size_t)8*DM;
    #pragma unroll
    for (int nv = 0; nv < 16; nv++) {
        const int d = nv*8 + 2*tig;
        float2 v0, v1;
        v0.x = oacc[nv][0]*inv0; v0.y = oacc[nv][1]*inv0;
        v1.x = oacc[nv][2]*inv1; v1.y = oacc[nv][3]*inv1;
        *(float2*)&O0[d] = v0;
        *(float2*)&O1[d] = v1;
    }
}

// ---------------------------------------------------------------------------

extern "C" void kernel_launch(void* const* d_in, const int* in_sizes, int n_in,
                              void* d_out, int out_size)
{
    const float* x    = (const float*)d_in[0];
    const float* Wqkv = (const float*)d_in[1];
    const float* bqkv = (const float*)d_in[2];
    const float* Wout = (const float*)d_in[3];
    const float* bout = (const float*)d_in[4];
    float* out = (float*)d_out;

    cudaFuncSetAttribute(attn_tc, cudaFuncAttributeMaxDynamicSharedMemorySize, ATTN_SMEM);

    // 1) QKV projection -> g_q/g_k/g_v  (TF32 tensor cores)
    dim3 g1(3*DM/128, MTOT/128);
    tgemm<0><<<g1, 256>>>(x, Wqkv, bqkv, nullptr, DM, 3*DM);

    // 2) Causal attention -> g_ao  (TF32 tensor cores, flash)
    dim3 g2(SEQ/128, NH, BATCH);
    attn_tc<<<g2, 256, ATTN_SMEM>>>();

    // 3) Output projection -> d_out  (TF32 tensor cores)
    dim3 g3(DM/128, MTOT/128);
    tgemm<1><<<g3, 256>>>(nullptr, Wout, bout, out, DM, DM);
}